// round 7
// baseline (speedup 1.0000x reference)
#include <cuda_runtime.h>
#include <cuda_bf16.h>

#define CH 96
#define HH 128
#define WW 128
#define BC 1536
#define NF 129
#define XP 144            // pitch for g_Krow
#define THREADS 512       // 32 groups of 16 threads

// digit-reversed base-4 position of output bin k after in-register fft16
#define P16(k) ((((k) & 3) << 2) | ((k) >> 2))

__device__ float2 g_Krow[CH * HH * XP];      // row-rFFT of k
__device__ float2 g_Kf  [CH * NF * 256];     // full 2D FFT of k  [c][f][m]

#define TILE_N   16512                       // 128 rows * 129 bins
#define SMEM_FLOATS (2*TILE_N)               // 132096 bytes (real+imag tiles)
#define TP 129                               // tile pitch (odd -> col access conflict-free)

// ---------------------------------------------------------------------------
template<int SGN>
__device__ __forceinline__ void fft4(float& r0, float& i0, float& r1, float& i1,
                                     float& r2, float& i2, float& r3, float& i3) {
    float t0r = r0 + r2, t0i = i0 + i2, t1r = r0 - r2, t1i = i0 - i2;
    float t2r = r1 + r3, t2i = i1 + i3, t3r = r1 - r3, t3i = i1 - i3;
    float w3r = (SGN < 0) ? t3i : -t3i;
    float w3i = (SGN < 0) ? -t3r : t3r;
    r0 = t0r + t2r; i0 = t0i + t2i;
    r2 = t0r - t2r; i2 = t0i - t2i;
    r1 = t1r + w3r; i1 = t1i + w3i;
    r3 = t1r - w3r; i3 = t1i - w3i;
}

template<int SGN>
__device__ __forceinline__ void fft16(float* r, float* im) {
    #pragma unroll
    for (int b = 0; b < 4; b++)
        fft4<SGN>(r[b], im[b], r[b+4], im[b+4], r[b+8], im[b+8], r[b+12], im[b+12]);
    const float TC[10] = {1.f, 0.92387953f, 0.70710678f, 0.38268343f, 0.f,
                          0.f, -0.70710678f, 0.f, 0.f, -0.92387953f};
    const float TS[10] = {0.f, 0.38268343f, 0.70710678f, 0.92387953f, 1.f,
                          0.f, 0.70710678f, 0.f, 0.f, -0.38268343f};
    #pragma unroll
    for (int k1 = 1; k1 < 4; k1++)
        #pragma unroll
        for (int b = 1; b < 4; b++) {
            const int m = k1 * b, p = 4 * k1 + b;
            const float c = TC[m], s = (float)SGN * TS[m];
            float vr = r[p] * c - im[p] * s;
            im[p]    = r[p] * s + im[p] * c;
            r[p]     = vr;
        }
    #pragma unroll
    for (int k1 = 0; k1 < 4; k1++)
        fft4<SGN>(r[4*k1], im[4*k1], r[4*k1+1], im[4*k1+1],
                  r[4*k1+2], im[4*k1+2], r[4*k1+3], im[4*k1+3]);
}

// 256-pt FFT by one 16-thread group, transpose done via shfl (no smem).
// Thread j enters with z[16*n1+j] natural; exits with X[16*k2+j] at P16(k2).
template<int SGN>
__device__ __forceinline__ void fft256_grp(float* zr, float* zi, int j) {
    fft16<SGN>(zr, zi);
    // twiddle W256^(j*k1), accumulate in natural-k1 order into u[]
    float ang = (float)SGN * (6.2831853071795864f / 256.f) * (float)j;
    float wjs, wjc;
    __sincosf(ang, &wjs, &wjc);
    float wr = 1.f, wi = 0.f;
    float ur[16], ui[16];
    #pragma unroll
    for (int k1 = 0; k1 < 16; k1++) {
        const int p = P16(k1);
        ur[k1] = zr[p] * wr - zi[p] * wi;
        ui[k1] = zr[p] * wi + zi[p] * wr;
        float nr = wr * wjc - wi * wjs;
        wi = wr * wjs + wi * wjc; wr = nr;
    }
    // 16x16 register transpose across the 16-lane group (XOR network)
    #pragma unroll
    for (int m = 1; m < 16; m <<= 1) {
        #pragma unroll
        for (int k0 = 0; k0 < 16; k0++) {
            if (k0 & m) continue;
            const int k1i = k0 | m;
            float sr_ = (j & m) ? ur[k0] : ur[k1i];
            float si_ = (j & m) ? ui[k0] : ui[k1i];
            float rr_ = __shfl_xor_sync(0xffffffffu, sr_, m);
            float ri_ = __shfl_xor_sync(0xffffffffu, si_, m);
            if (j & m) { ur[k0]  = rr_; ui[k0]  = ri_; }
            else       { ur[k1i] = rr_; ui[k1i] = ri_; }
        }
    }
    fft16<SGN>(ur, ui);
    #pragma unroll
    for (int k = 0; k < 16; k++) { zr[k] = ur[k]; zi[k] = ui[k]; }
}

// ---------------------------------------------------------------------------
// Kernel A: MLP -> k values -> row rFFT.  grid = CH*8, 16 rows per block.
__global__ void __launch_bounds__(256)
krow_kernel(const float* __restrict__ W1, const float* __restrict__ b1,
            const float* __restrict__ W2, const float* __restrict__ b2) {
    const int t = threadIdx.x, g = t >> 4, j = t & 15;
    const int c = blockIdx.x >> 3;
    const int r = ((blockIdx.x & 7) << 4) + g;
    float w1a[16], w1b[16], bb1[16], w2[16];
    #pragma unroll
    for (int h = 0; h < 16; h++) {
        w1a[h] = W1[h]; w1b[h] = W1[16 + h]; bb1[h] = b1[h]; w2[h] = W2[h * CH + c];
    }
    const float bias = b2[c];
    const float gy = (float)r * (1.f / 127.f);
    float zr[16], zi[16];
    #pragma unroll
    for (int n1 = 0; n1 < 16; n1++) {
        const int col = n1 * 16 + j;
        float v = 0.f;
        if (col < 128) {
            const float gx = (float)col * (1.f / 127.f);
            float acc = bias;
            #pragma unroll
            for (int h = 0; h < 16; h++)
                acc += fmaxf(gy * w1a[h] + gx * w1b[h] + bb1[h], 0.f) * w2[h];
            v = acc;
        }
        zr[n1] = v; zi[n1] = 0.f;
    }
    fft256_grp<-1>(zr, zi, j);
    const int base = (c * HH + r) * XP;
    #pragma unroll
    for (int k2 = 0; k2 < 8; k2++)
        g_Krow[base + k2*16 + j] = make_float2(zr[P16(k2)], zi[P16(k2)]);
    if (j == 0)
        g_Krow[base + 128] = make_float2(zr[P16(8)], zi[P16(8)]);
}

// Kernel B: column FFT of k.  grid = CH*9.
__global__ void __launch_bounds__(256)
kcol_kernel() {
    const int t = threadIdx.x, g = t >> 4, j = t & 15;
    const int c = blockIdx.x / 9;
    const int f = (blockIdx.x % 9) * 16 + g;
    const bool act = (f <= 128);
    float zr[16], zi[16];
    #pragma unroll
    for (int n1 = 0; n1 < 16; n1++) {
        const int row = n1 * 16 + j;
        float2 v = make_float2(0.f, 0.f);
        if (act && row < 128) v = g_Krow[(c * HH + row) * XP + f];
        zr[n1] = v.x; zi[n1] = v.y;
    }
    fft256_grp<-1>(zr, zi, j);
    if (act) {
        const int base = (c * NF + f) * 256;
        #pragma unroll
        for (int k2 = 0; k2 < 16; k2++)
            g_Kf[base + k2*16 + j] = make_float2(zr[P16(k2)], zi[P16(k2)]);
    }
}

// ---------------------------------------------------------------------------
// Fused per-image kernel. One block = one image. 32 groups of 16 threads.
// Phase 1: packed-real row rFFTs (row pairs).  Phase 2: col FFT * Kf * col
// iFFT.  Phase 3: packed-real hermitian row inverse + residual.
// ---------------------------------------------------------------------------
__global__ void __launch_bounds__(THREADS)
fused_kernel(const float* __restrict__ x, float* __restrict__ out) {
    extern __shared__ float smem[];
    float* tr = smem;
    float* ti = smem + TILE_N;

    const int t = threadIdx.x, g = t >> 4, j = t & 15;
    const int bc = blockIdx.x;
    const int c  = bc % CH;

    // ---- Phase 1: 64 packed row rFFTs (2 iters of 32 groups) ----
    #pragma unroll 1
    for (int it = 0; it < 2; it++) {
        const int rA = it * 32 + g;        // rows rA and rA+64 packed together
        const int rB = rA + 64;
        const int xa = (bc * HH + rA) * WW;
        const int xb = (bc * HH + rB) * WW;
        float zr[16], zi[16];
        #pragma unroll
        for (int n1 = 0; n1 < 16; n1++) {
            const int col = n1 * 16 + j;
            if (col < 128) { zr[n1] = x[xa + col]; zi[n1] = x[xb + col]; }
            else           { zr[n1] = 0.f;         zi[n1] = 0.f; }
        }
        fft256_grp<-1>(zr, zi, j);
        // unpack: A = (Z[k]+conj(Z[256-k]))/2 ; B = (Z[k]-conj(Z[256-k]))/(2i)
        const int baseA = rA * TP, baseB = rB * TP;
        #pragma unroll
        for (int k2 = 0; k2 < 8; k2++) {
            float sr_ = zr[P16(15 - k2)], si_ = zi[P16(15 - k2)];
            float mr_ = __shfl_sync(0xffffffffu, sr_, (16 - j) & 15, 16);
            float mi_ = __shfl_sync(0xffffffffu, si_, (16 - j) & 15, 16);
            if (j == 0) { mr_ = zr[P16((16 - k2) & 15)]; mi_ = zi[P16((16 - k2) & 15)]; }
            const float zkr = zr[P16(k2)], zki = zi[P16(k2)];
            tr[baseA + k2*16 + j] = 0.5f * (zkr + mr_);
            ti[baseA + k2*16 + j] = 0.5f * (zki - mi_);
            tr[baseB + k2*16 + j] = 0.5f * (zki + mi_);
            ti[baseB + k2*16 + j] = 0.5f * (mr_ - zkr);
        }
        if (j == 0) {                       // bin 128 (self-mirror)
            tr[baseA + 128] = zr[P16(8)];  ti[baseA + 128] = 0.f;
            tr[baseB + 128] = zi[P16(8)];  ti[baseB + 128] = 0.f;
        }
    }
    __syncthreads();

    // ---- Phase 2: per-column fwd FFT * Kf * inv FFT (129 cols, 5 iters) ----
    #pragma unroll 1
    for (int it = 0; it < 5; it++) {
        const int f = it * 32 + g;
        const bool act = (f <= 128);
        float zr[16], zi[16];
        #pragma unroll
        for (int n1 = 0; n1 < 16; n1++) {
            const int row = n1 * 16 + j;          // rows >=128 are zero pad
            if (act && row < 128) {
                zr[n1] = tr[row * TP + f];
                zi[n1] = ti[row * TP + f];
            } else { zr[n1] = 0.f; zi[n1] = 0.f; }
        }
        fft256_grp<-1>(zr, zi, j);                // forward along column
        if (act) {
            const int kb = (c * NF + f) * 256;
            #pragma unroll
            for (int k2 = 0; k2 < 16; k2++) {
                const float2 kv = g_Kf[kb + k2*16 + j];
                const int p = P16(k2);
                const float a = zr[p], b = zi[p];
                zr[p] = a * kv.x - b * kv.y;
                zi[p] = a * kv.y + b * kv.x;
            }
        }
        float yr[16], yi[16];
        #pragma unroll
        for (int n1 = 0; n1 < 16; n1++) { yr[n1] = zr[P16(n1)]; yi[n1] = zi[P16(n1)]; }
        fft256_grp<1>(yr, yi, j);                 // unnormalized inverse
        if (act) {
            #pragma unroll
            for (int k2 = 0; k2 < 8; k2++) {      // keep only rows 0..127
                const int row = k2 * 16 + j;
                tr[row * TP + f] = yr[P16(k2)];
                ti[row * TP + f] = yi[P16(k2)];
            }
        }
    }
    __syncthreads();

    // ---- Phase 3: 64 packed hermitian row inverses + residual (2 iters) ----
    #pragma unroll 1
    for (int it = 0; it < 2; it++) {
        const int rA = it * 32 + g;
        const int rB = rA + 64;
        const int baseA = rA * TP, baseB = rB * TP;
        float zr[16], zi[16];
        #pragma unroll
        for (int n1 = 0; n1 < 16; n1++) {
            const int n = n1 * 16 + j;
            float Ar, Ai, Br, Bi;
            if (n <= 128) {
                Ar = tr[baseA + n]; Ai = ti[baseA + n];
                Br = tr[baseB + n]; Bi = ti[baseB + n];
            } else {
                const int m2 = 256 - n;            // hermitian mirror
                Ar = tr[baseA + m2]; Ai = -ti[baseA + m2];
                Br = tr[baseB + m2]; Bi = -ti[baseB + m2];
            }
            zr[n1] = Ar - Bi;                      // Z = A + i*B
            zi[n1] = Ai + Br;
        }
        fft256_grp<1>(zr, zi, j);                  // z[n] = a[n] + i*b[n]
        const int ga = (bc * HH + rA) * WW;
        const int gb = (bc * HH + rB) * WW;
        #pragma unroll
        for (int k2 = 0; k2 < 8; k2++) {
            const int col = k2 * 16 + j;
            out[ga + col] = zr[P16(k2)] + x[ga + col];
            out[gb + col] = zi[P16(k2)] + x[gb + col];
        }
    }
}

// ---------------------------------------------------------------------------
extern "C" void kernel_launch(void* const* d_in, const int* in_sizes, int n_in,
                              void* d_out, int out_size) {
    const float* x  = (const float*)d_in[0];
    const float* W1 = (const float*)d_in[1];
    const float* b1 = (const float*)d_in[2];
    const float* W2 = (const float*)d_in[3];
    const float* b2 = (const float*)d_in[4];
    float* out = (float*)d_out;

    static int smem_set = 0;
    if (!smem_set) {
        cudaFuncSetAttribute(fused_kernel,
                             cudaFuncAttributeMaxDynamicSharedMemorySize,
                             SMEM_FLOATS * (int)sizeof(float));
        smem_set = 1;
    }

    krow_kernel<<<CH * 8, 256>>>(W1, b1, W2, b2);
    kcol_kernel<<<CH * 9, 256>>>();
    fused_kernel<<<BC, THREADS, SMEM_FLOATS * sizeof(float)>>>(x, out);
}

// round 8
// speedup vs baseline: 1.2084x; 1.2084x over previous
#include <cuda_runtime.h>
#include <cuda_bf16.h>

#define CH 96
#define HH 128
#define WW 128
#define BC 1536
#define NF 129
#define XP 144            // pitch for g_Krow
#define THREADS 512       // 32 groups of 16 threads

// digit-reversed base-4 position of output bin k after in-register fft16
#define P16(k) ((((k) & 3) << 2) | ((k) >> 2))

__device__ float2 g_Krow[CH * HH * XP];      // row-rFFT of k
__device__ float2 g_Kf  [CH * NF * 256];     // full 2D FFT of k  [c][f][m]

#define TILE_N   16512                       // 128 rows * 129 bins
#define SCR_N    8704                        // 32 groups * 272
#define SMEM_FLOATS (2*TILE_N + 2*SCR_N)     // 201728 bytes
#define TP 129                               // tile pitch (odd -> col access conflict-free)

// ---------------------------------------------------------------------------
template<int SGN>
__device__ __forceinline__ void fft4(float& r0, float& i0, float& r1, float& i1,
                                     float& r2, float& i2, float& r3, float& i3) {
    float t0r = r0 + r2, t0i = i0 + i2, t1r = r0 - r2, t1i = i0 - i2;
    float t2r = r1 + r3, t2i = i1 + i3, t3r = r1 - r3, t3i = i1 - i3;
    float w3r = (SGN < 0) ? t3i : -t3i;
    float w3i = (SGN < 0) ? -t3r : t3r;
    r0 = t0r + t2r; i0 = t0i + t2i;
    r2 = t0r - t2r; i2 = t0i - t2i;
    r1 = t1r + w3r; i1 = t1i + w3i;
    r3 = t1r - w3r; i3 = t1i - w3i;
}

template<int SGN>
__device__ __forceinline__ void fft16(float* r, float* im) {
    #pragma unroll
    for (int b = 0; b < 4; b++)
        fft4<SGN>(r[b], im[b], r[b+4], im[b+4], r[b+8], im[b+8], r[b+12], im[b+12]);
    const float TC[10] = {1.f, 0.92387953f, 0.70710678f, 0.38268343f, 0.f,
                          0.f, -0.70710678f, 0.f, 0.f, -0.92387953f};
    const float TS[10] = {0.f, 0.38268343f, 0.70710678f, 0.92387953f, 1.f,
                          0.f, 0.70710678f, 0.f, 0.f, -0.38268343f};
    #pragma unroll
    for (int k1 = 1; k1 < 4; k1++)
        #pragma unroll
        for (int b = 1; b < 4; b++) {
            const int m = k1 * b, p = 4 * k1 + b;
            const float c = TC[m], s = (float)SGN * TS[m];
            float vr = r[p] * c - im[p] * s;
            im[p]    = r[p] * s + im[p] * c;
            r[p]     = vr;
        }
    #pragma unroll
    for (int k1 = 0; k1 < 4; k1++)
        fft4<SGN>(r[4*k1], im[4*k1], r[4*k1+1], im[4*k1+1],
                  r[4*k1+2], im[4*k1+2], r[4*k1+3], im[4*k1+3]);
}

// 256-pt FFT by one 16-thread group; thread j enters with z[16*n1+j] natural,
// exits with X[16*k2+j] at position P16(k2). sr/si: per-group 272-float scratch.
template<int SGN>
__device__ __forceinline__ void fft256_grp(float* zr, float* zi,
                                           float* sr, float* si, int j) {
    fft16<SGN>(zr, zi);
    float ang = (float)SGN * (6.2831853071795864f / 256.f) * (float)j;
    float wjs, wjc;
    __sincosf(ang, &wjs, &wjc);
    float wr = 1.f, wi = 0.f;
    __syncwarp();
    #pragma unroll
    for (int k1 = 0; k1 < 16; k1++) {
        const int p = P16(k1);
        sr[k1 * 17 + j] = zr[p] * wr - zi[p] * wi;
        si[k1 * 17 + j] = zr[p] * wi + zi[p] * wr;
        float nr = wr * wjc - wi * wjs;
        wi = wr * wjs + wi * wjc; wr = nr;
    }
    __syncwarp();
    #pragma unroll
    for (int n2 = 0; n2 < 16; n2++) { zr[n2] = sr[j*17 + n2]; zi[n2] = si[j*17 + n2]; }
    fft16<SGN>(zr, zi);
}

// ---------------------------------------------------------------------------
// Kernel A: MLP -> k values -> row rFFT.  grid = CH*8, 16 rows per block.
__global__ void __launch_bounds__(256)
krow_kernel(const float* __restrict__ W1, const float* __restrict__ b1,
            const float* __restrict__ W2, const float* __restrict__ b2) {
    __shared__ float s_r[16*272], s_i[16*272];
    const int t = threadIdx.x, g = t >> 4, j = t & 15;
    const int c = blockIdx.x >> 3;
    const int r = ((blockIdx.x & 7) << 4) + g;
    float w1a[16], w1b[16], bb1[16], w2[16];
    #pragma unroll
    for (int h = 0; h < 16; h++) {
        w1a[h] = W1[h]; w1b[h] = W1[16 + h]; bb1[h] = b1[h]; w2[h] = W2[h * CH + c];
    }
    const float bias = b2[c];
    const float gy = (float)r * (1.f / 127.f);
    float zr[16], zi[16];
    #pragma unroll
    for (int n1 = 0; n1 < 16; n1++) {
        const int col = n1 * 16 + j;
        float v = 0.f;
        if (col < 128) {
            const float gx = (float)col * (1.f / 127.f);
            float acc = bias;
            #pragma unroll
            for (int h = 0; h < 16; h++)
                acc += fmaxf(gy * w1a[h] + gx * w1b[h] + bb1[h], 0.f) * w2[h];
            v = acc;
        }
        zr[n1] = v; zi[n1] = 0.f;
    }
    fft256_grp<-1>(zr, zi, s_r + g*272, s_i + g*272, j);
    const int base = (c * HH + r) * XP;
    #pragma unroll
    for (int k2 = 0; k2 < 8; k2++)
        g_Krow[base + k2*16 + j] = make_float2(zr[P16(k2)], zi[P16(k2)]);
    if (j == 0)
        g_Krow[base + 128] = make_float2(zr[P16(8)], zi[P16(8)]);
}

// Kernel B: column FFT of k.  grid = CH*9.
__global__ void __launch_bounds__(256)
kcol_kernel() {
    __shared__ float s_r[16*272], s_i[16*272];
    const int t = threadIdx.x, g = t >> 4, j = t & 15;
    const int c = blockIdx.x / 9;
    const int f = (blockIdx.x % 9) * 16 + g;
    const bool act = (f <= 128);
    float zr[16], zi[16];
    #pragma unroll
    for (int n1 = 0; n1 < 16; n1++) {
        const int row = n1 * 16 + j;
        float2 v = make_float2(0.f, 0.f);
        if (act && row < 128) v = g_Krow[(c * HH + row) * XP + f];
        zr[n1] = v.x; zi[n1] = v.y;
    }
    fft256_grp<-1>(zr, zi, s_r + g*272, s_i + g*272, j);
    if (act) {
        const int base = (c * NF + f) * 256;
        #pragma unroll
        for (int k2 = 0; k2 < 16; k2++)
            g_Kf[base + k2*16 + j] = make_float2(zr[P16(k2)], zi[P16(k2)]);
    }
}

// ---------------------------------------------------------------------------
// Fused per-image kernel. One block = one image. 32 groups of 16 threads.
// Phase 1: packed-real row rFFTs (row pairs).  Phase 2: col FFT * Kf * col
// iFFT.  Phase 3: packed-real hermitian row inverse + residual.
// ---------------------------------------------------------------------------
__global__ void __launch_bounds__(THREADS)
fused_kernel(const float* __restrict__ x, float* __restrict__ out) {
    extern __shared__ float smem[];
    float* tr = smem;
    float* ti = smem + TILE_N;
    float* fr = smem + 2*TILE_N;
    float* fi = smem + 2*TILE_N + SCR_N;

    const int t = threadIdx.x, g = t >> 4, j = t & 15;
    const int bc = blockIdx.x;
    const int c  = bc % CH;
    float* sr = fr + g*272;
    float* si = fi + g*272;

    // ---- Phase 1: 64 packed row rFFTs (rows r and r+64), 2 iters ----
    #pragma unroll 1
    for (int it = 0; it < 2; it++) {
        const int rA = it * 32 + g;
        const int rB = rA + 64;
        const int xa = (bc * HH + rA) * WW;
        const int xb = (bc * HH + rB) * WW;
        float zr[16], zi[16];
        #pragma unroll
        for (int n1 = 0; n1 < 16; n1++) {
            const int col = n1 * 16 + j;
            if (col < 128) { zr[n1] = x[xa + col]; zi[n1] = x[xb + col]; }
            else           { zr[n1] = 0.f;         zi[n1] = 0.f; }
        }
        fft256_grp<-1>(zr, zi, sr, si, j);
        // unpack: A = (Z[k]+conj(Z[256-k]))/2 ; B = (Z[k]-conj(Z[256-k]))/(2i)
        const int baseA = rA * TP, baseB = rB * TP;
        #pragma unroll
        for (int k2 = 0; k2 < 8; k2++) {
            float sr_ = zr[P16(15 - k2)], si_ = zi[P16(15 - k2)];
            float mr_ = __shfl_sync(0xffffffffu, sr_, (16 - j) & 15, 16);
            float mi_ = __shfl_sync(0xffffffffu, si_, (16 - j) & 15, 16);
            if (j == 0) { mr_ = zr[P16((16 - k2) & 15)]; mi_ = zi[P16((16 - k2) & 15)]; }
            const float zkr = zr[P16(k2)], zki = zi[P16(k2)];
            tr[baseA + k2*16 + j] = 0.5f * (zkr + mr_);
            ti[baseA + k2*16 + j] = 0.5f * (zki - mi_);
            tr[baseB + k2*16 + j] = 0.5f * (zki + mi_);
            ti[baseB + k2*16 + j] = 0.5f * (mr_ - zkr);
        }
        if (j == 0) {                        // bin 128 (self-mirror)
            tr[baseA + 128] = zr[P16(8)];  ti[baseA + 128] = 0.f;
            tr[baseB + 128] = zi[P16(8)];  ti[baseB + 128] = 0.f;
        }
    }
    __syncthreads();

    // ---- Phase 2: per-column fwd FFT * Kf * inv FFT (129 cols, 5 iters) ----
    #pragma unroll 1
    for (int it = 0; it < 5; it++) {
        const int f = it * 32 + g;
        const bool act = (f <= 128);
        float zr[16], zi[16];
        #pragma unroll
        for (int n1 = 0; n1 < 16; n1++) {
            const int row = n1 * 16 + j;          // rows >=128 are zero pad
            if (act && row < 128) {
                zr[n1] = tr[row * TP + f];
                zi[n1] = ti[row * TP + f];
            } else { zr[n1] = 0.f; zi[n1] = 0.f; }
        }
        fft256_grp<-1>(zr, zi, sr, si, j);        // forward along column
        // multiply by Kf, writing straight into natural order for the inverse
        float yr[16], yi[16];
        if (act) {
            const int kb = (c * NF + f) * 256;
            #pragma unroll
            for (int k2 = 0; k2 < 16; k2++) {
                const float2 kv = g_Kf[kb + k2*16 + j];
                const int p = P16(k2);
                const float a = zr[p], b = zi[p];
                yr[k2] = a * kv.x - b * kv.y;
                yi[k2] = a * kv.y + b * kv.x;
            }
        } else {
            #pragma unroll
            for (int k2 = 0; k2 < 16; k2++) { yr[k2] = 0.f; yi[k2] = 0.f; }
        }
        fft256_grp<1>(yr, yi, sr, si, j);         // unnormalized inverse
        if (act) {
            #pragma unroll
            for (int k2 = 0; k2 < 8; k2++) {      // keep only rows 0..127
                const int row = k2 * 16 + j;
                tr[row * TP + f] = yr[P16(k2)];
                ti[row * TP + f] = yi[P16(k2)];
            }
        }
    }
    __syncthreads();

    // ---- Phase 3: 64 packed hermitian row inverses + residual (2 iters) ----
    #pragma unroll 1
    for (int it = 0; it < 2; it++) {
        const int rA = it * 32 + g;
        const int rB = rA + 64;
        const int baseA = rA * TP, baseB = rB * TP;
        float zr[16], zi[16];
        #pragma unroll
        for (int n1 = 0; n1 < 16; n1++) {
            const int n = n1 * 16 + j;
            float Ar, Ai, Br, Bi;
            if (n <= 128) {
                Ar = tr[baseA + n]; Ai = ti[baseA + n];
                Br = tr[baseB + n]; Bi = ti[baseB + n];
            } else {
                const int m2 = 256 - n;            // hermitian mirror
                Ar = tr[baseA + m2]; Ai = -ti[baseA + m2];
                Br = tr[baseB + m2]; Bi = -ti[baseB + m2];
            }
            zr[n1] = Ar - Bi;                      // Z = A + i*B
            zi[n1] = Ai + Br;
        }
        fft256_grp<1>(zr, zi, sr, si, j);          // z[n] = a[n] + i*b[n]
        const int ga = (bc * HH + rA) * WW;
        const int gb = (bc * HH + rB) * WW;
        #pragma unroll
        for (int k2 = 0; k2 < 8; k2++) {
            const int col = k2 * 16 + j;
            out[ga + col] = zr[P16(k2)] + x[ga + col];
            out[gb + col] = zi[P16(k2)] + x[gb + col];
        }
    }
}

// ---------------------------------------------------------------------------
extern "C" void kernel_launch(void* const* d_in, const int* in_sizes, int n_in,
                              void* d_out, int out_size) {
    const float* x  = (const float*)d_in[0];
    const float* W1 = (const float*)d_in[1];
    const float* b1 = (const float*)d_in[2];
    const float* W2 = (const float*)d_in[3];
    const float* b2 = (const float*)d_in[4];
    float* out = (float*)d_out;

    static int smem_set = 0;
    if (!smem_set) {
        cudaFuncSetAttribute(fused_kernel,
                             cudaFuncAttributeMaxDynamicSharedMemorySize,
                             SMEM_FLOATS * (int)sizeof(float));
        smem_set = 1;
    }

    krow_kernel<<<CH * 8, 256>>>(W1, b1, W2, b2);
    kcol_kernel<<<CH * 9, 256>>>();
    fused_kernel<<<BC, THREADS, SMEM_FLOATS * sizeof(float)>>>(x, out);
}